// round 2
// baseline (speedup 1.0000x reference)
#include <cuda_runtime.h>
#include <cuda_bf16.h>
#include <math.h>

// Problem constants
#define S    2048
#define D    2048
#define NH   32
#define NKV  8
#define HD   64
#define QKV_N 3072   // (32 + 16) * 64

// ---------------------------------------------------------------------------
// Scratch (device globals — no allocation allowed)
// ---------------------------------------------------------------------------
__device__ float g_qkv[(size_t)S * QKV_N];      // [s, 3072]
__device__ float g_q[(size_t)NH * S * HD];      // [h, s, d]
__device__ float g_k[(size_t)NKV * S * HD];     // [kh, s, d]
__device__ float g_v[(size_t)NKV * S * HD];     // [kh, s, d]
__device__ float g_attn[(size_t)S * D];         // [s, h*64+d]

// ---------------------------------------------------------------------------
// GEMM: C[M,N] = A[M,K] @ B[N,K]^T, 128x128 tile, BK=16, 256 threads,
// 8x8 micro-tile via 2x float4 fragments, double-buffered smem.
// ---------------------------------------------------------------------------
__global__ __launch_bounds__(256) void gemm_nt(const float* __restrict__ A,
                                               const float* __restrict__ B,
                                               float* __restrict__ C,
                                               int M, int N, int K) {
    __shared__ float As[2][16][128];
    __shared__ float Bs[2][16][128];

    const int tid = threadIdx.x;
    const int tr  = tid / 16;           // 0..15
    const int tc  = tid % 16;           // 0..15
    const int rowA0 = blockIdx.y * 128;
    const int colB0 = blockIdx.x * 128;
    const int lrow = tid >> 2;          // 0..63
    const int lcol = (tid & 3) * 4;     // 0,4,8,12

    float acc[8][8];
#pragma unroll
    for (int i = 0; i < 8; i++)
#pragma unroll
        for (int j = 0; j < 8; j++) acc[i][j] = 0.f;

    float4 va[2], vb[2];

    // Preload tile 0
#pragma unroll
    for (int i = 0; i < 2; i++) {
        va[i] = *(const float4*)&A[(size_t)(rowA0 + lrow + i * 64) * K + lcol];
        vb[i] = *(const float4*)&B[(size_t)(colB0 + lrow + i * 64) * K + lcol];
    }
#pragma unroll
    for (int i = 0; i < 2; i++) {
        int r = lrow + i * 64;
        As[0][lcol + 0][r] = va[i].x; As[0][lcol + 1][r] = va[i].y;
        As[0][lcol + 2][r] = va[i].z; As[0][lcol + 3][r] = va[i].w;
        Bs[0][lcol + 0][r] = vb[i].x; Bs[0][lcol + 1][r] = vb[i].y;
        Bs[0][lcol + 2][r] = vb[i].z; Bs[0][lcol + 3][r] = vb[i].w;
    }
    __syncthreads();

    for (int k0 = 0; k0 < K; k0 += 16) {
        const int buf  = (k0 >> 4) & 1;
        const bool more = (k0 + 16) < K;

        if (more) {
#pragma unroll
            for (int i = 0; i < 2; i++) {
                va[i] = *(const float4*)&A[(size_t)(rowA0 + lrow + i * 64) * K + k0 + 16 + lcol];
                vb[i] = *(const float4*)&B[(size_t)(colB0 + lrow + i * 64) * K + k0 + 16 + lcol];
            }
        }

#pragma unroll
        for (int kk = 0; kk < 16; kk++) {
            float4 a0 = *(const float4*)&As[buf][kk][tr * 4];
            float4 a1 = *(const float4*)&As[buf][kk][64 + tr * 4];
            float4 b0 = *(const float4*)&Bs[buf][kk][tc * 4];
            float4 b1 = *(const float4*)&Bs[buf][kk][64 + tc * 4];
            float a[8] = {a0.x, a0.y, a0.z, a0.w, a1.x, a1.y, a1.z, a1.w};
            float b[8] = {b0.x, b0.y, b0.z, b0.w, b1.x, b1.y, b1.z, b1.w};
#pragma unroll
            for (int i = 0; i < 8; i++)
#pragma unroll
                for (int j = 0; j < 8; j++) acc[i][j] += a[i] * b[j];
        }

        if (more) {
            const int nb = buf ^ 1;
#pragma unroll
            for (int i = 0; i < 2; i++) {
                int r = lrow + i * 64;
                As[nb][lcol + 0][r] = va[i].x; As[nb][lcol + 1][r] = va[i].y;
                As[nb][lcol + 2][r] = va[i].z; As[nb][lcol + 3][r] = va[i].w;
                Bs[nb][lcol + 0][r] = vb[i].x; Bs[nb][lcol + 1][r] = vb[i].y;
                Bs[nb][lcol + 2][r] = vb[i].z; Bs[nb][lcol + 3][r] = vb[i].w;
            }
        }
        __syncthreads();
    }

#pragma unroll
    for (int i = 0; i < 8; i++) {
        int row = rowA0 + ((i < 4) ? (tr * 4 + i) : (64 + tr * 4 + i - 4));
        float4 c0 = make_float4(acc[i][0], acc[i][1], acc[i][2], acc[i][3]);
        float4 c1 = make_float4(acc[i][4], acc[i][5], acc[i][6], acc[i][7]);
        *(float4*)&C[(size_t)row * N + colB0 + tc * 4]      = c0;
        *(float4*)&C[(size_t)row * N + colB0 + 64 + tc * 4] = c1;
    }
}

// ---------------------------------------------------------------------------
// RoPE on Q and K, scatter to [head, seq, hd]; V copied to [kh, seq, hd].
// ---------------------------------------------------------------------------
__global__ __launch_bounds__(256) void rope_scatter(const float* __restrict__ qkv,
                                                    const float* __restrict__ fc,
                                                    float* __restrict__ Qo,
                                                    float* __restrict__ Ko,
                                                    float* __restrict__ Vo) {
    const int s   = blockIdx.x;
    const int tid = threadIdx.x;
    const float* row = qkv + (size_t)s * QKV_N;

    for (int i = tid; i < NH * (HD / 2); i += 256) {
        int h = i >> 5, d2 = i & 31;
        float x0 = row[h * HD + 2 * d2];
        float x1 = row[h * HD + 2 * d2 + 1];
        float c  = fc[s * HD + 2 * d2];
        float sn = fc[s * HD + 2 * d2 + 1];
        float* dst = Qo + ((size_t)h * S + s) * HD + 2 * d2;
        dst[0] = x0 * c - x1 * sn;
        dst[1] = x1 * c + x0 * sn;
    }
    {
        int h = tid >> 5, d2 = tid & 31;
        float x0 = row[D + h * HD + 2 * d2];
        float x1 = row[D + h * HD + 2 * d2 + 1];
        float c  = fc[s * HD + 2 * d2];
        float sn = fc[s * HD + 2 * d2 + 1];
        float* dst = Ko + ((size_t)h * S + s) * HD + 2 * d2;
        dst[0] = x0 * c - x1 * sn;
        dst[1] = x1 * c + x0 * sn;
    }
    for (int i = tid; i < NKV * HD; i += 256) {
        int h = i >> 6, d = i & 63;
        Vo[((size_t)h * S + s) * HD + d] = row[D + NKV * HD + i];
    }
}

// ---------------------------------------------------------------------------
// Causal flash attention (fp32), spill-free.
// Block: 256 threads (8 warps). Each warp: 8 query rows x 4 lanes/row.
// Lane owns 16 of 64 head dims (q, acc) and 16 of 64 tile scores.
// Two-phase per tile: (1) dots w/ shuffle reduce, (2) softmax, (3) PV accum
// with score broadcast via shuffle.
// ---------------------------------------------------------------------------
#define AT_BQ 64
#define AT_TK 64

__global__ __launch_bounds__(256) void flash_attn(const float* __restrict__ Qm,
                                                  const float* __restrict__ Km,
                                                  const float* __restrict__ Vm,
                                                  float* __restrict__ O) {
    __shared__ float Ks[AT_TK][HD];
    __shared__ float Vs[AT_TK][HD];

    const int h    = blockIdx.y;
    const int kh   = h >> 2;                     // GQA
    const int qb   = gridDim.x - 1 - blockIdx.x; // big blocks first
    const int tid  = threadIdx.x;
    const int warp = tid >> 5;
    const int lane = tid & 31;
    const int r    = lane >> 2;                  // row within warp: 0..7
    const int g    = lane & 3;                   // dim group: 0..3
    const int qi   = qb * AT_BQ + warp * 8 + r;

    const float* qp = Qm + ((size_t)h * S + qi) * HD + g * 16;
    float4 q0 = *(const float4*)(qp + 0);
    float4 q1 = *(const float4*)(qp + 4);
    float4 q2 = *(const float4*)(qp + 8);
    float4 q3 = *(const float4*)(qp + 12);
    float4 acc0 = {0,0,0,0}, acc1 = {0,0,0,0}, acc2 = {0,0,0,0}, acc3 = {0,0,0,0};
    float m = -1e30f, l = 0.f;

    const int ntiles = qb + 1;
    for (int t = 0; t < ntiles; t++) {
        const int kv0 = t * AT_TK;
        // cooperative K/V tile loads: 64x64 floats each
#pragma unroll
        for (int i = 0; i < 4; i++) {
            int idx = tid + i * 256;
            int row = idx >> 4, c4 = (idx & 15) * 4;
            *(float4*)&Ks[row][c4] =
                *(const float4*)&Km[((size_t)kh * S + kv0 + row) * HD + c4];
            *(float4*)&Vs[row][c4] =
                *(const float4*)&Vm[((size_t)kh * S + kv0 + row) * HD + c4];
        }
        __syncthreads();

        float sreg[16];
        // Phase 1: scores. Lane g keeps scores for j in [g*16, g*16+16)
#pragma unroll
        for (int jo = 0; jo < 4; jo++) {
#pragma unroll
            for (int ji = 0; ji < 16; ji++) {
                const int j = jo * 16 + ji;
                const float* kp = &Ks[j][g * 16];
                float4 k0 = *(const float4*)(kp + 0);
                float4 k1 = *(const float4*)(kp + 4);
                float4 k2 = *(const float4*)(kp + 8);
                float4 k3 = *(const float4*)(kp + 12);
                float s0 = q0.x*k0.x + q0.y*k0.y + q0.z*k0.z + q0.w*k0.w;
                float s1 = q1.x*k1.x + q1.y*k1.y + q1.z*k1.z + q1.w*k1.w;
                float s2 = q2.x*k2.x + q2.y*k2.y + q2.z*k2.z + q2.w*k2.w;
                float s3 = q3.x*k3.x + q3.y*k3.y + q3.z*k3.z + q3.w*k3.w;
                float sv = (s0 + s1) + (s2 + s3);
                sv += __shfl_xor_sync(0xffffffffu, sv, 1);
                sv += __shfl_xor_sync(0xffffffffu, sv, 2);
                sv *= 0.125f;                         // 1/sqrt(64)
                if (kv0 + j > qi) sv = -1e30f;        // causal
                if (g == jo) sreg[ji] = sv;
            }
        }

        // Phase 2: online softmax update
        float tmax = sreg[0];
#pragma unroll
        for (int i = 1; i < 16; i++) tmax = fmaxf(tmax, sreg[i]);
        tmax = fmaxf(tmax, __shfl_xor_sync(0xffffffffu, tmax, 1));
        tmax = fmaxf(tmax, __shfl_xor_sync(0xffffffffu, tmax, 2));
        const float mnew  = fmaxf(m, tmax);
        const float scale = __expf(m - mnew);
        l *= scale;
        acc0.x *= scale; acc0.y *= scale; acc0.z *= scale; acc0.w *= scale;
        acc1.x *= scale; acc1.y *= scale; acc1.z *= scale; acc1.w *= scale;
        acc2.x *= scale; acc2.y *= scale; acc2.z *= scale; acc2.w *= scale;
        acc3.x *= scale; acc3.y *= scale; acc3.z *= scale; acc3.w *= scale;
        float lsum = 0.f;
#pragma unroll
        for (int i = 0; i < 16; i++) {
            sreg[i] = __expf(sreg[i] - mnew);
            lsum += sreg[i];
        }
        lsum += __shfl_xor_sync(0xffffffffu, lsum, 1);
        lsum += __shfl_xor_sync(0xffffffffu, lsum, 2);
        l += lsum;
        m = mnew;

        // Phase 3: acc += P @ V (broadcast p from owner lane)
        const int base = lane & 0x1C;
#pragma unroll
        for (int jo = 0; jo < 4; jo++) {
            const int src = base | jo;
#pragma unroll
            for (int ji = 0; ji < 16; ji++) {
                float p = __shfl_sync(0xffffffffu, sreg[ji], src);
                const float* vp = &Vs[jo * 16 + ji][g * 16];
                float4 v0 = *(const float4*)(vp + 0);
                float4 v1 = *(const float4*)(vp + 4);
                float4 v2 = *(const float4*)(vp + 8);
                float4 v3 = *(const float4*)(vp + 12);
                acc0.x += p*v0.x; acc0.y += p*v0.y; acc0.z += p*v0.z; acc0.w += p*v0.w;
                acc1.x += p*v1.x; acc1.y += p*v1.y; acc1.z += p*v1.z; acc1.w += p*v1.w;
                acc2.x += p*v2.x; acc2.y += p*v2.y; acc2.z += p*v2.z; acc2.w += p*v2.w;
                acc3.x += p*v3.x; acc3.y += p*v3.y; acc3.z += p*v3.z; acc3.w += p*v3.w;
            }
        }
        __syncthreads();
    }

    const float inv = 1.f / l;
    float* op = O + (size_t)qi * D + h * HD + g * 16;
    float4 o0 = make_float4(acc0.x*inv, acc0.y*inv, acc0.z*inv, acc0.w*inv);
    float4 o1 = make_float4(acc1.x*inv, acc1.y*inv, acc1.z*inv, acc1.w*inv);
    float4 o2 = make_float4(acc2.x*inv, acc2.y*inv, acc2.z*inv, acc2.w*inv);
    float4 o3 = make_float4(acc3.x*inv, acc3.y*inv, acc3.z*inv, acc3.w*inv);
    *(float4*)(op + 0)  = o0;
    *(float4*)(op + 4)  = o1;
    *(float4*)(op + 8)  = o2;
    *(float4*)(op + 12) = o3;
}

// ---------------------------------------------------------------------------
// Launch
// ---------------------------------------------------------------------------
extern "C" void kernel_launch(void* const* d_in, const int* in_sizes, int n_in,
                              void* d_out, int out_size) {
    const float* hs   = (const float*)d_in[0];   // [1, 2048, 2048]
    const float* fc   = (const float*)d_in[1];   // [2048, 32, 2]
    const float* wqkv = (const float*)d_in[2];   // [3072, 2048]
    const float* wo   = (const float*)d_in[3];   // [2048, 2048]
    float* out = (float*)d_out;                  // [1, 2048, 2048]

    float *p_qkv, *p_q, *p_k, *p_v, *p_attn;
    cudaGetSymbolAddress((void**)&p_qkv,  g_qkv);
    cudaGetSymbolAddress((void**)&p_q,    g_q);
    cudaGetSymbolAddress((void**)&p_k,    g_k);
    cudaGetSymbolAddress((void**)&p_v,    g_v);
    cudaGetSymbolAddress((void**)&p_attn, g_attn);

    // 1) qkv = hs @ wqkv^T
    gemm_nt<<<dim3(QKV_N / 128, S / 128), 256>>>(hs, wqkv, p_qkv, S, QKV_N, D);
    // 2) RoPE + scatter
    rope_scatter<<<S, 256>>>(p_qkv, fc, p_q, p_k, p_v);
    // 3) causal attention
    flash_attn<<<dim3(S / AT_BQ, NH), 256>>>(p_q, p_k, p_v, p_attn);
    // 4) out = attn @ wo^T
    gemm_nt<<<dim3(D / 128, S / 128), 256>>>(p_attn, wo, out, S, D, D);
}

// round 4
// speedup vs baseline: 2.2476x; 2.2476x over previous
#include <cuda_runtime.h>
#include <cuda_bf16.h>
#include <math.h>
#include <stdint.h>

// Problem constants
#define S    2048
#define D    2048
#define NH   32
#define NKV  8
#define HD   64
#define QKV_N 3072   // (32 + 16) * 64

// ---------------------------------------------------------------------------
// Scratch (device globals — no allocation allowed)
// ---------------------------------------------------------------------------
__device__ float g_qkv[(size_t)S * QKV_N];      // [s, 3072]
__device__ float g_q[(size_t)NH * S * HD];      // [h, s, d]
__device__ float g_k[(size_t)NKV * S * HD];     // [kh, s, d]
__device__ float g_v[(size_t)NKV * S * HD];     // [kh, s, d]
__device__ float g_attn[(size_t)S * D];         // [s, h*64+d]

__device__ __forceinline__ uint32_t to_tf32(float x) {
    float r;
    asm("cvt.rna.tf32.f32 %0, %1;" : "=f"(r) : "f"(x));
    return __float_as_uint(r);
}

__device__ __forceinline__ void mma_tf32(float* d, const uint32_t* a, const uint32_t* b) {
    asm volatile(
        "mma.sync.aligned.m16n8k8.row.col.f32.tf32.tf32.f32 "
        "{%0,%1,%2,%3}, {%4,%5,%6,%7}, {%8,%9}, {%0,%1,%2,%3};"
        : "+f"(d[0]), "+f"(d[1]), "+f"(d[2]), "+f"(d[3])
        : "r"(a[0]), "r"(a[1]), "r"(a[2]), "r"(a[3]), "r"(b[0]), "r"(b[1]));
}

// ---------------------------------------------------------------------------
// Tensor-core tf32 GEMM: C[M,N] = A[M,K] @ B[N,K]^T.
// CTA tile 128x128, 256 threads = 8 warps in 2(m) x 4(n); warp tile 64x32.
// K consumed in 16-wide tiles, double-buffered smem, pad-20 row stride
// (conflict-free fragment loads: bank = (20g + t) % 32 distinct for all lanes).
// ---------------------------------------------------------------------------
#define KT  16
#define LDP 20

__global__ __launch_bounds__(256) void gemm_mma(const float* __restrict__ A,
                                                const float* __restrict__ B,
                                                float* __restrict__ C,
                                                int M, int N, int K) {
    __shared__ uint32_t As[2][128 * LDP];
    __shared__ uint32_t Bs[2][128 * LDP];

    const int tid  = threadIdx.x;
    const int lane = tid & 31;
    const int wid  = tid >> 5;
    const int wm   = wid >> 2;          // 0..1
    const int wn   = wid & 3;           // 0..3
    const int g    = lane >> 2;         // 0..7
    const int t    = lane & 3;          // 0..3
    const int row0 = blockIdx.y * 128;
    const int col0 = blockIdx.x * 128;

    // per-thread load coords: 512 float4 per operand per tile
    const int lr = tid >> 2;            // 0..63 (+64 on second pass)
    const int lc = (tid & 3) * 4;       // 0,4,8,12

    float acc[4][4][4];
#pragma unroll
    for (int mi = 0; mi < 4; mi++)
#pragma unroll
        for (int ni = 0; ni < 4; ni++)
#pragma unroll
            for (int e = 0; e < 4; e++) acc[mi][ni][e] = 0.f;

    float4 va[2], vb[2];

    // preload k-tile 0
#pragma unroll
    for (int i = 0; i < 2; i++) {
        va[i] = *(const float4*)&A[(size_t)(row0 + lr + i * 64) * K + lc];
        vb[i] = *(const float4*)&B[(size_t)(col0 + lr + i * 64) * K + lc];
    }
#pragma unroll
    for (int i = 0; i < 2; i++) {
        const int r = lr + i * 64;
        uint32_t* pa = &As[0][r * LDP + lc];
        uint32_t* pb = &Bs[0][r * LDP + lc];
        pa[0] = to_tf32(va[i].x); pa[1] = to_tf32(va[i].y);
        pa[2] = to_tf32(va[i].z); pa[3] = to_tf32(va[i].w);
        pb[0] = to_tf32(vb[i].x); pb[1] = to_tf32(vb[i].y);
        pb[2] = to_tf32(vb[i].z); pb[3] = to_tf32(vb[i].w);
    }
    __syncthreads();

    const int NT = K / KT;
    for (int it = 0; it < NT; it++) {
        const int buf  = it & 1;
        const bool more = (it + 1) < NT;

        if (more) {
            const int k0 = (it + 1) * KT;
#pragma unroll
            for (int i = 0; i < 2; i++) {
                va[i] = *(const float4*)&A[(size_t)(row0 + lr + i * 64) * K + k0 + lc];
                vb[i] = *(const float4*)&B[(size_t)(col0 + lr + i * 64) * K + k0 + lc];
            }
        }

        const uint32_t* as = As[buf];
        const uint32_t* bs = Bs[buf];
#pragma unroll
        for (int kk = 0; kk < KT; kk += 8) {
            uint32_t af[4][4], bf[4][2];
#pragma unroll
            for (int mi = 0; mi < 4; mi++) {
                const int r = wm * 64 + mi * 16 + g;
                af[mi][0] = as[r * LDP + kk + t];
                af[mi][1] = as[(r + 8) * LDP + kk + t];
                af[mi][2] = as[r * LDP + kk + t + 4];
                af[mi][3] = as[(r + 8) * LDP + kk + t + 4];
            }
#pragma unroll
            for (int ni = 0; ni < 4; ni++) {
                const int r = wn * 32 + ni * 8 + g;
                bf[ni][0] = bs[r * LDP + kk + t];
                bf[ni][1] = bs[r * LDP + kk + t + 4];
            }
#pragma unroll
            for (int mi = 0; mi < 4; mi++)
#pragma unroll
                for (int ni = 0; ni < 4; ni++)
                    mma_tf32(acc[mi][ni], af[mi], bf[ni]);
        }

        if (more) {
            const int nb = buf ^ 1;
#pragma unroll
            for (int i = 0; i < 2; i++) {
                const int r = lr + i * 64;
                uint32_t* pa = &As[nb][r * LDP + lc];
                uint32_t* pb = &Bs[nb][r * LDP + lc];
                pa[0] = to_tf32(va[i].x); pa[1] = to_tf32(va[i].y);
                pa[2] = to_tf32(va[i].z); pa[3] = to_tf32(va[i].w);
                pb[0] = to_tf32(vb[i].x); pb[1] = to_tf32(vb[i].y);
                pb[2] = to_tf32(vb[i].z); pb[3] = to_tf32(vb[i].w);
            }
        }
        __syncthreads();
    }

    // epilogue: c0=(g,2t), c1=(g,2t+1), c2=(g+8,2t), c3=(g+8,2t+1)
#pragma unroll
    for (int mi = 0; mi < 4; mi++) {
        const int row = row0 + wm * 64 + mi * 16 + g;
#pragma unroll
        for (int ni = 0; ni < 4; ni++) {
            const int col = col0 + wn * 32 + ni * 8 + 2 * t;
            *(float2*)&C[(size_t)row * N + col] =
                make_float2(acc[mi][ni][0], acc[mi][ni][1]);
            *(float2*)&C[(size_t)(row + 8) * N + col] =
                make_float2(acc[mi][ni][2], acc[mi][ni][3]);
        }
    }
}

// ---------------------------------------------------------------------------
// RoPE on Q and K, scatter to [head, seq, hd]; V copied to [kh, seq, hd].
// ---------------------------------------------------------------------------
__global__ __launch_bounds__(256) void rope_scatter(const float* __restrict__ qkv,
                                                    const float* __restrict__ fc,
                                                    float* __restrict__ Qo,
                                                    float* __restrict__ Ko,
                                                    float* __restrict__ Vo) {
    const int s   = blockIdx.x;
    const int tid = threadIdx.x;
    const float* row = qkv + (size_t)s * QKV_N;

    for (int i = tid; i < NH * (HD / 2); i += 256) {
        int h = i >> 5, d2 = i & 31;
        float x0 = row[h * HD + 2 * d2];
        float x1 = row[h * HD + 2 * d2 + 1];
        float c  = fc[s * HD + 2 * d2];
        float sn = fc[s * HD + 2 * d2 + 1];
        float* dst = Qo + ((size_t)h * S + s) * HD + 2 * d2;
        dst[0] = x0 * c - x1 * sn;
        dst[1] = x1 * c + x0 * sn;
    }
    {
        int h = tid >> 5, d2 = tid & 31;
        float x0 = row[D + h * HD + 2 * d2];
        float x1 = row[D + h * HD + 2 * d2 + 1];
        float c  = fc[s * HD + 2 * d2];
        float sn = fc[s * HD + 2 * d2 + 1];
        float* dst = Ko + ((size_t)h * S + s) * HD + 2 * d2;
        dst[0] = x0 * c - x1 * sn;
        dst[1] = x1 * c + x0 * sn;
    }
    for (int i = tid; i < NKV * HD; i += 256) {
        int h = i >> 6, d = i & 63;
        Vo[((size_t)h * S + s) * HD + d] = row[D + NKV * HD + i];
    }
}

// ---------------------------------------------------------------------------
// Causal flash attention (fp32) — R1 structure, __expf for softmax.
// ---------------------------------------------------------------------------
#define BQ 128
#define TK 32

__global__ __launch_bounds__(BQ) void flash_attn(const float* __restrict__ Qm,
                                                 const float* __restrict__ Km,
                                                 const float* __restrict__ Vm,
                                                 float* __restrict__ O) {
    __shared__ float Ks[TK][HD];
    __shared__ float Vs[TK][HD];

    const int h   = blockIdx.y;
    const int kh  = h >> 2;
    const int qb  = blockIdx.x;
    const int tid = threadIdx.x;
    const int qi  = qb * BQ + tid;

    float q[HD], acc[HD];
#pragma unroll
    for (int d = 0; d < HD; d++) {
        q[d]   = Qm[((size_t)h * S + qi) * HD + d];
        acc[d] = 0.f;
    }
    float m = -1e30f, l = 0.f;

    const int kv_end = (qb + 1) * BQ;
    for (int kv0 = 0; kv0 < kv_end; kv0 += TK) {
#pragma unroll
        for (int i = 0; i < 4; i++) {
            int idx = tid + i * BQ;
            int r = idx >> 4, c4 = (idx & 15) * 4;
            *(float4*)&Ks[r][c4] =
                *(const float4*)&Km[((size_t)kh * S + kv0 + r) * HD + c4];
            *(float4*)&Vs[r][c4] =
                *(const float4*)&Vm[((size_t)kh * S + kv0 + r) * HD + c4];
        }
        __syncthreads();

        float sreg[TK];
        float tmax = -1e30f;
#pragma unroll
        for (int j = 0; j < TK; j++) {
            float sv = 0.f;
#pragma unroll
            for (int d = 0; d < HD; d++) sv += q[d] * Ks[j][d];
            sv *= 0.125f;
            if (kv0 + j > qi) sv = -1e30f;
            sreg[j] = sv;
            tmax = fmaxf(tmax, sv);
        }
        float mnew  = fmaxf(m, tmax);
        float scale = __expf(m - mnew);
        l *= scale;
#pragma unroll
        for (int d = 0; d < HD; d++) acc[d] *= scale;
#pragma unroll
        for (int j = 0; j < TK; j++) {
            float p = __expf(sreg[j] - mnew);
            l += p;
#pragma unroll
            for (int d = 0; d < HD; d++) acc[d] += p * Vs[j][d];
        }
        m = mnew;
        __syncthreads();
    }

    float inv = 1.f / l;
#pragma unroll
    for (int d = 0; d < HD; d++)
        O[(size_t)qi * D + h * HD + d] = acc[d] * inv;
}

// ---------------------------------------------------------------------------
// Launch
// ---------------------------------------------------------------------------
extern "C" void kernel_launch(void* const* d_in, const int* in_sizes, int n_in,
                              void* d_out, int out_size) {
    const float* hs   = (const float*)d_in[0];   // [1, 2048, 2048]
    const float* fc   = (const float*)d_in[1];   // [2048, 32, 2]
    const float* wqkv = (const float*)d_in[2];   // [3072, 2048]
    const float* wo   = (const float*)d_in[3];   // [2048, 2048]
    float* out = (float*)d_out;                  // [1, 2048, 2048]

    float *p_qkv, *p_q, *p_k, *p_v, *p_attn;
    cudaGetSymbolAddress((void**)&p_qkv,  g_qkv);
    cudaGetSymbolAddress((void**)&p_q,    g_q);
    cudaGetSymbolAddress((void**)&p_k,    g_k);
    cudaGetSymbolAddress((void**)&p_v,    g_v);
    cudaGetSymbolAddress((void**)&p_attn, g_attn);

    // 1) qkv = hs @ wqkv^T : M=2048, N=3072, K=2048
    gemm_mma<<<dim3(QKV_N / 128, S / 128), 256>>>(hs, wqkv, p_qkv, S, QKV_N, D);
    // 2) RoPE + scatter
    rope_scatter<<<S, 256>>>(p_qkv, fc, p_q, p_k, p_v);
    // 3) causal attention
    flash_attn<<<dim3(S / BQ, NH), BQ>>>(p_q, p_k, p_v, p_attn);
    // 4) out = attn @ wo^T : M=N=K=2048
    gemm_mma<<<dim3(D / 128, S / 128), 256>>>(p_attn, wo, out, S, D, D);
}

// round 5
// speedup vs baseline: 6.8184x; 3.0337x over previous
#include <cuda_runtime.h>
#include <cuda_fp16.h>
#include <math.h>
#include <stdint.h>

// Problem constants
#define S    2048
#define D    2048
#define NH   32
#define NKV  8
#define HD   64
#define QKV_N 3072   // (32 + 16) * 64

// ---------------------------------------------------------------------------
// Scratch (device globals — no allocation allowed)
// ---------------------------------------------------------------------------
__device__ float  g_qkv[(size_t)S * QKV_N];       // [s, 3072]
__device__ __half g_qh [(size_t)NH  * S * HD];    // [h, s, d]   (pre-scaled)
__device__ __half g_kh [(size_t)NKV * S * HD];    // [kh, s, d]
__device__ __half g_vth[(size_t)NKV * HD * S];    // [kh, d, s]  (transposed)
__device__ float  g_attn[(size_t)S * D];          // [s, h*64+d]

__device__ __forceinline__ uint32_t to_tf32(float x) {
    float r;
    asm("cvt.rna.tf32.f32 %0, %1;" : "=f"(r) : "f"(x));
    return __float_as_uint(r);
}

__device__ __forceinline__ void mma_tf32(float* d, const uint32_t* a, const uint32_t* b) {
    asm volatile(
        "mma.sync.aligned.m16n8k8.row.col.f32.tf32.tf32.f32 "
        "{%0,%1,%2,%3}, {%4,%5,%6,%7}, {%8,%9}, {%0,%1,%2,%3};"
        : "+f"(d[0]), "+f"(d[1]), "+f"(d[2]), "+f"(d[3])
        : "r"(a[0]), "r"(a[1]), "r"(a[2]), "r"(a[3]), "r"(b[0]), "r"(b[1]));
}

__device__ __forceinline__ void mma_f16(float* d, const uint32_t* a,
                                        uint32_t b0, uint32_t b1) {
    asm volatile(
        "mma.sync.aligned.m16n8k16.row.col.f32.f16.f16.f32 "
        "{%0,%1,%2,%3}, {%4,%5,%6,%7}, {%8,%9}, {%0,%1,%2,%3};"
        : "+f"(d[0]), "+f"(d[1]), "+f"(d[2]), "+f"(d[3])
        : "r"(a[0]), "r"(a[1]), "r"(a[2]), "r"(a[3]), "r"(b0), "r"(b1));
}

__device__ __forceinline__ uint32_t ex2_h2(uint32_t x) {
    uint32_t r;
    asm("ex2.approx.f16x2 %0, %1;" : "=r"(r) : "r"(x));
    return r;
}
__device__ __forceinline__ uint32_t pack_h2(float lo, float hi) {
    __half2 h = __floats2half2_rn(lo, hi);
    return *(uint32_t*)&h;
}

// ---------------------------------------------------------------------------
// Tensor-core tf32 GEMM (unchanged from R4): C[M,N] = A[M,K] @ B[N,K]^T
// ---------------------------------------------------------------------------
#define KT  16
#define LDP 20

__global__ __launch_bounds__(256) void gemm_mma(const float* __restrict__ A,
                                                const float* __restrict__ B,
                                                float* __restrict__ C,
                                                int M, int N, int K) {
    __shared__ uint32_t As[2][128 * LDP];
    __shared__ uint32_t Bs[2][128 * LDP];

    const int tid  = threadIdx.x;
    const int lane = tid & 31;
    const int wid  = tid >> 5;
    const int wm   = wid >> 2;
    const int wn   = wid & 3;
    const int g    = lane >> 2;
    const int t    = lane & 3;
    const int row0 = blockIdx.y * 128;
    const int col0 = blockIdx.x * 128;
    const int lr = tid >> 2;
    const int lc = (tid & 3) * 4;

    float acc[4][4][4];
#pragma unroll
    for (int mi = 0; mi < 4; mi++)
#pragma unroll
        for (int ni = 0; ni < 4; ni++)
#pragma unroll
            for (int e = 0; e < 4; e++) acc[mi][ni][e] = 0.f;

    float4 va[2], vb[2];
#pragma unroll
    for (int i = 0; i < 2; i++) {
        va[i] = *(const float4*)&A[(size_t)(row0 + lr + i * 64) * K + lc];
        vb[i] = *(const float4*)&B[(size_t)(col0 + lr + i * 64) * K + lc];
    }
#pragma unroll
    for (int i = 0; i < 2; i++) {
        const int r = lr + i * 64;
        uint32_t* pa = &As[0][r * LDP + lc];
        uint32_t* pb = &Bs[0][r * LDP + lc];
        pa[0] = to_tf32(va[i].x); pa[1] = to_tf32(va[i].y);
        pa[2] = to_tf32(va[i].z); pa[3] = to_tf32(va[i].w);
        pb[0] = to_tf32(vb[i].x); pb[1] = to_tf32(vb[i].y);
        pb[2] = to_tf32(vb[i].z); pb[3] = to_tf32(vb[i].w);
    }
    __syncthreads();

    const int NT = K / KT;
    for (int it = 0; it < NT; it++) {
        const int buf  = it & 1;
        const bool more = (it + 1) < NT;

        if (more) {
            const int k0 = (it + 1) * KT;
#pragma unroll
            for (int i = 0; i < 2; i++) {
                va[i] = *(const float4*)&A[(size_t)(row0 + lr + i * 64) * K + k0 + lc];
                vb[i] = *(const float4*)&B[(size_t)(col0 + lr + i * 64) * K + k0 + lc];
            }
        }

        const uint32_t* as = As[buf];
        const uint32_t* bs = Bs[buf];
#pragma unroll
        for (int kk = 0; kk < KT; kk += 8) {
            uint32_t af[4][4], bf[4][2];
#pragma unroll
            for (int mi = 0; mi < 4; mi++) {
                const int r = wm * 64 + mi * 16 + g;
                af[mi][0] = as[r * LDP + kk + t];
                af[mi][1] = as[(r + 8) * LDP + kk + t];
                af[mi][2] = as[r * LDP + kk + t + 4];
                af[mi][3] = as[(r + 8) * LDP + kk + t + 4];
            }
#pragma unroll
            for (int ni = 0; ni < 4; ni++) {
                const int r = wn * 32 + ni * 8 + g;
                bf[ni][0] = bs[r * LDP + kk + t];
                bf[ni][1] = bs[r * LDP + kk + t + 4];
            }
#pragma unroll
            for (int mi = 0; mi < 4; mi++)
#pragma unroll
                for (int ni = 0; ni < 4; ni++)
                    mma_tf32(acc[mi][ni], af[mi], bf[ni]);
        }

        if (more) {
            const int nb = buf ^ 1;
#pragma unroll
            for (int i = 0; i < 2; i++) {
                const int r = lr + i * 64;
                uint32_t* pa = &As[nb][r * LDP + lc];
                uint32_t* pb = &Bs[nb][r * LDP + lc];
                pa[0] = to_tf32(va[i].x); pa[1] = to_tf32(va[i].y);
                pa[2] = to_tf32(va[i].z); pa[3] = to_tf32(va[i].w);
                pb[0] = to_tf32(vb[i].x); pb[1] = to_tf32(vb[i].y);
                pb[2] = to_tf32(vb[i].z); pb[3] = to_tf32(vb[i].w);
            }
        }
        __syncthreads();
    }

#pragma unroll
    for (int mi = 0; mi < 4; mi++) {
        const int row = row0 + wm * 64 + mi * 16 + g;
#pragma unroll
        for (int ni = 0; ni < 4; ni++) {
            const int col = col0 + wn * 32 + ni * 8 + 2 * t;
            *(float2*)&C[(size_t)row * N + col] =
                make_float2(acc[mi][ni][0], acc[mi][ni][1]);
            *(float2*)&C[(size_t)(row + 8) * N + col] =
                make_float2(acc[mi][ni][2], acc[mi][ni][3]);
        }
    }
}

// ---------------------------------------------------------------------------
// RoPE -> fp16 tensors for attention.
//   Qh [h][s][d]  : rotated q * (0.125 * log2(e))   (score scale prefolded)
//   Kh [kh][s][d] : rotated k
//   Vth[kh][d][s] : v transposed
// ---------------------------------------------------------------------------
#define QSCALE 0.18033688011112042f   // 0.125 * log2(e)

__global__ __launch_bounds__(256) void rope_fp16(const float* __restrict__ qkv,
                                                 const float* __restrict__ fc,
                                                 __half* __restrict__ Qh,
                                                 __half* __restrict__ Kh,
                                                 __half* __restrict__ Vth) {
    const int s   = blockIdx.x;
    const int tid = threadIdx.x;
    const float* row = qkv + (size_t)s * QKV_N;

    // Q: 32 heads * 32 pairs = 1024
    for (int i = tid; i < NH * (HD / 2); i += 256) {
        int h = i >> 5, d2 = i & 31;
        float x0 = row[h * HD + 2 * d2];
        float x1 = row[h * HD + 2 * d2 + 1];
        float c  = fc[s * HD + 2 * d2];
        float sn = fc[s * HD + 2 * d2 + 1];
        float y0 = (x0 * c - x1 * sn) * QSCALE;
        float y1 = (x1 * c + x0 * sn) * QSCALE;
        *(__half2*)&Qh[((size_t)h * S + s) * HD + 2 * d2] = __floats2half2_rn(y0, y1);
    }
    // K: 8 heads * 32 pairs = 256
    {
        int h = tid >> 5, d2 = tid & 31;
        float x0 = row[D + h * HD + 2 * d2];
        float x1 = row[D + h * HD + 2 * d2 + 1];
        float c  = fc[s * HD + 2 * d2];
        float sn = fc[s * HD + 2 * d2 + 1];
        float y0 = x0 * c - x1 * sn;
        float y1 = x1 * c + x0 * sn;
        *(__half2*)&Kh[((size_t)h * S + s) * HD + 2 * d2] = __floats2half2_rn(y0, y1);
    }
    // V transposed: 512 elements
    for (int i = tid; i < NKV * HD; i += 256) {
        int h = i >> 6, d = i & 63;
        Vth[((size_t)h * HD + d) * S + s] = __float2half_rn(row[D + NKV * HD + i]);
    }
}

// ---------------------------------------------------------------------------
// Tensor-core causal flash attention (fp16 mma, fp32 acc, no-max softmax).
// Block: 256 thr / 8 warps, 128 q-rows per block (16 per warp), one head.
// KV tiles of 64. P obtained via ex2.approx.f16x2 directly in A-frag layout.
// Row sums l accumulated by an extra MMA against ones.
// ---------------------------------------------------------------------------
#define AQ 128
#define AK 64
#define KLD 88   // half stride: 176B, 16B-aligned, conflict-free frag loads

__global__ __launch_bounds__(256) void attn_mma(const __half* __restrict__ Qh,
                                                const __half* __restrict__ Kh,
                                                const __half* __restrict__ Vth,
                                                float* __restrict__ O) {
    __shared__ __half Ks[AK][KLD];   // [kv][d]
    __shared__ __half Vs[HD][KLD];   // [d][kv]

    const int h    = blockIdx.y;
    const int kh   = h >> 2;
    const int qb   = gridDim.x - 1 - blockIdx.x;   // big blocks first
    const int tid  = threadIdx.x;
    const int lane = tid & 31;
    const int w    = tid >> 5;
    const int g    = lane >> 2;
    const int t    = lane & 3;
    const int bq   = qb * AQ + w * 16;             // warp's first q row

    // Q fragments from global (row-major, adjacent halves)
    uint32_t qf[4][4];
    const __half* Qr0 = Qh + ((size_t)h * S + bq + g) * HD;
    const __half* Qr8 = Qr0 + 8 * HD;
#pragma unroll
    for (int kc = 0; kc < 4; kc++) {
        qf[kc][0] = *(const uint32_t*)(Qr0 + 16 * kc + 2 * t);
        qf[kc][1] = *(const uint32_t*)(Qr8 + 16 * kc + 2 * t);
        qf[kc][2] = *(const uint32_t*)(Qr0 + 16 * kc + 2 * t + 8);
        qf[kc][3] = *(const uint32_t*)(Qr8 + 16 * kc + 2 * t + 8);
    }

    float o[8][4];
#pragma unroll
    for (int nn = 0; nn < 8; nn++)
#pragma unroll
        for (int e = 0; e < 4; e++) o[nn][e] = 0.f;
    float lacc[4] = {0.f, 0.f, 0.f, 0.f};
    const uint32_t ONES = 0x3C003C00u;

    const int ntiles = (qb + 1) * (AQ / AK);
    for (int tt = 0; tt < ntiles; tt++) {
        const int kv0 = tt * AK;
        // cooperative loads: K tile 64x64, Vt tile 64x64 (halves)
#pragma unroll
        for (int i = 0; i < 2; i++) {
            const int idx = tid + i * 256;
            const int r = idx >> 3, c = (idx & 7) * 8;
            *(float4*)&Ks[r][c] =
                *(const float4*)&Kh[((size_t)kh * S + kv0 + r) * HD + c];
            *(float4*)&Vs[r][c] =
                *(const float4*)&Vth[((size_t)kh * HD + r) * S + kv0 + c];
        }
        __syncthreads();

        if (kv0 <= bq + 15) {   // warp-uniform: tile not fully masked
            // --- QK^T ---
            float sc[8][4];
#pragma unroll
            for (int nn = 0; nn < 8; nn++) {
                sc[nn][0] = sc[nn][1] = sc[nn][2] = sc[nn][3] = 0.f;
#pragma unroll
                for (int kc = 0; kc < 4; kc++) {
                    uint32_t b0 = *(const uint32_t*)&Ks[nn * 8 + g][16 * kc + 2 * t];
                    uint32_t b1 = *(const uint32_t*)&Ks[nn * 8 + g][16 * kc + 2 * t + 8];
                    mma_f16(sc[nn], qf[kc], b0, b1);
                }
            }
            // --- causal mask (only when tile straddles the diagonal) ---
            if (kv0 + AK - 1 > bq) {
                const int rg  = bq + g;
                const int rg8 = rg + 8;
#pragma unroll
                for (int nn = 0; nn < 8; nn++) {
                    const int col = kv0 + nn * 8 + 2 * t;
                    if (col     > rg ) sc[nn][0] = -30.f;
                    if (col + 1 > rg ) sc[nn][1] = -30.f;
                    if (col     > rg8) sc[nn][2] = -30.f;
                    if (col + 1 > rg8) sc[nn][3] = -30.f;
                }
            }
            // --- p = 2^s in half2, already in A-frag layout ---
            uint32_t p[8][2];
#pragma unroll
            for (int nn = 0; nn < 8; nn++) {
                p[nn][0] = ex2_h2(pack_h2(sc[nn][0], sc[nn][1]));
                p[nn][1] = ex2_h2(pack_h2(sc[nn][2], sc[nn][3]));
            }
            // --- l += P @ ones ; O += P @ V ---
#pragma unroll
            for (int c = 0; c < 4; c++) {
                uint32_t a[4] = {p[2 * c][0], p[2 * c][1],
                                 p[2 * c + 1][0], p[2 * c + 1][1]};
                mma_f16(lacc, a, ONES, ONES);
#pragma unroll
                for (int nn = 0; nn < 8; nn++) {
                    uint32_t b0 = *(const uint32_t*)&Vs[nn * 8 + g][16 * c + 2 * t];
                    uint32_t b1 = *(const uint32_t*)&Vs[nn * 8 + g][16 * c + 2 * t + 8];
                    mma_f16(o[nn], a, b0, b1);
                }
            }
        }
        __syncthreads();
    }

    // all columns of the ones-MMA result are identical: c0 = l(row g), c2 = l(row g+8)
    const float invg  = 1.f / lacc[0];
    const float invg8 = 1.f / lacc[2];
#pragma unroll
    for (int nn = 0; nn < 8; nn++) {
        const int col = h * HD + nn * 8 + 2 * t;
        *(float2*)&O[(size_t)(bq + g) * D + col] =
            make_float2(o[nn][0] * invg, o[nn][1] * invg);
        *(float2*)&O[(size_t)(bq + g + 8) * D + col] =
            make_float2(o[nn][2] * invg8, o[nn][3] * invg8);
    }
}

// ---------------------------------------------------------------------------
// Launch
// ---------------------------------------------------------------------------
extern "C" void kernel_launch(void* const* d_in, const int* in_sizes, int n_in,
                              void* d_out, int out_size) {
    const float* hs   = (const float*)d_in[0];   // [1, 2048, 2048]
    const float* fc   = (const float*)d_in[1];   // [2048, 32, 2]
    const float* wqkv = (const float*)d_in[2];   // [3072, 2048]
    const float* wo   = (const float*)d_in[3];   // [2048, 2048]
    float* out = (float*)d_out;                  // [1, 2048, 2048]

    float *p_qkv, *p_attn;
    __half *p_qh, *p_kh, *p_vth;
    cudaGetSymbolAddress((void**)&p_qkv,  g_qkv);
    cudaGetSymbolAddress((void**)&p_qh,   g_qh);
    cudaGetSymbolAddress((void**)&p_kh,   g_kh);
    cudaGetSymbolAddress((void**)&p_vth,  g_vth);
    cudaGetSymbolAddress((void**)&p_attn, g_attn);

    // 1) qkv = hs @ wqkv^T
    gemm_mma<<<dim3(QKV_N / 128, S / 128), 256>>>(hs, wqkv, p_qkv, S, QKV_N, D);
    // 2) RoPE -> fp16 Q (pre-scaled), K, V^T
    rope_fp16<<<S, 256>>>(p_qkv, fc, p_qh, p_kh, p_vth);
    // 3) tensor-core causal attention
    attn_mma<<<dim3(S / AQ, NH), 256>>>(p_qh, p_kh, p_vth, p_attn);
    // 4) out = attn @ wo^T
    gemm_mma<<<dim3(D / 128, S / 128), 256>>>(p_attn, wo, out, S, D, D);
}

// round 6
// speedup vs baseline: 11.2614x; 1.6516x over previous
#include <cuda_runtime.h>
#include <cuda_fp16.h>
#include <math.h>
#include <stdint.h>

// Problem constants
#define S    2048
#define D    2048
#define NH   32
#define NKV  8
#define HD   64
#define QKV_N 3072   // (32 + 16) * 64

// ---------------------------------------------------------------------------
// Scratch (device globals — no allocation allowed)
// ---------------------------------------------------------------------------
__device__ float  g_qkv[(size_t)S * QKV_N];       // [s, 3072] f32
__device__ __half g_hsh  [(size_t)S * D];         // hs in fp16
__device__ __half g_wqkvh[(size_t)QKV_N * D];     // wqkv in fp16
__device__ __half g_woh  [(size_t)D * D];         // wo in fp16
__device__ __half g_qh [(size_t)NH  * S * HD];    // [h, s, d] (pre-scaled)
__device__ __half g_kh [(size_t)NKV * S * HD];    // [kh, s, d]
__device__ __half g_vth[(size_t)NKV * HD * S];    // [kh, d, s] (transposed)
__device__ __half g_attnh[(size_t)S * D];         // attention out, fp16

__device__ __forceinline__ void mma_f16(float* d, const uint32_t* a,
                                        uint32_t b0, uint32_t b1) {
    asm volatile(
        "mma.sync.aligned.m16n8k16.row.col.f32.f16.f16.f32 "
        "{%0,%1,%2,%3}, {%4,%5,%6,%7}, {%8,%9}, {%0,%1,%2,%3};"
        : "+f"(d[0]), "+f"(d[1]), "+f"(d[2]), "+f"(d[3])
        : "r"(a[0]), "r"(a[1]), "r"(a[2]), "r"(a[3]), "r"(b0), "r"(b1));
}

__device__ __forceinline__ uint32_t ex2_h2(uint32_t x) {
    uint32_t r;
    asm("ex2.approx.f16x2 %0, %1;" : "=r"(r) : "r"(x));
    return r;
}
__device__ __forceinline__ uint32_t pack_h2(float lo, float hi) {
    __half2 h = __floats2half2_rn(lo, hi);
    return *(uint32_t*)&h;
}

// ---------------------------------------------------------------------------
// f32 -> f16 conversion (float4 granularity)
// ---------------------------------------------------------------------------
__global__ __launch_bounds__(256) void cvt_h(const float* __restrict__ src,
                                             __half* __restrict__ dst, int n4) {
    int i = blockIdx.x * 256 + threadIdx.x;
    if (i < n4) {
        float4 v = ((const float4*)src)[i];
        __half2 h01 = __floats2half2_rn(v.x, v.y);
        __half2 h23 = __floats2half2_rn(v.z, v.w);
        ((uint2*)dst)[i] = make_uint2(*(uint32_t*)&h01, *(uint32_t*)&h23);
    }
}

// ---------------------------------------------------------------------------
// fp16 tensor-core GEMM: C[M,N](f32) = A[M,K](f16) @ B[N,K](f16)^T.
// CTA 128x128, 8 warps (2m x 4n), warp tile 64x32, k-tile 32 halves (64B rows),
// double-buffered smem with XOR-chunk swizzle (conflict-free STS.128 + LDS.32).
// ---------------------------------------------------------------------------
#define SWOFF(row, b) ((row) * 64 + (((((b) >> 4) ^ (((row) >> 1) & 3)) << 4) | ((b) & 15)))

__global__ __launch_bounds__(256) void gemm_h(const __half* __restrict__ A,
                                              const __half* __restrict__ B,
                                              float* __restrict__ C,
                                              int M, int N, int K) {
    __shared__ __align__(16) char As[2][128 * 64];
    __shared__ __align__(16) char Bs[2][128 * 64];

    const int tid  = threadIdx.x;
    const int lane = tid & 31;
    const int wid  = tid >> 5;
    const int wm   = wid >> 2;          // 0..1
    const int wn   = wid & 3;           // 0..3
    const int g    = lane >> 2;         // 0..7
    const int t    = lane & 3;          // 0..3
    const int row0 = blockIdx.y * 128;
    const int col0 = blockIdx.x * 128;

    // loader coords: 2 chunks of 16B per thread per operand
    const int lr0 = tid >> 2;           // rows 0..63 (i=0), +64 (i=1)
    const int lc  = tid & 3;            // 16B chunk within row

    float acc[4][4][4];
#pragma unroll
    for (int mi = 0; mi < 4; mi++)
#pragma unroll
        for (int ni = 0; ni < 4; ni++)
#pragma unroll
            for (int e = 0; e < 4; e++) acc[mi][ni][e] = 0.f;

    uint4 va[2], vb[2];
    // preload k-tile 0
#pragma unroll
    for (int i = 0; i < 2; i++) {
        const int r = lr0 + i * 64;
        va[i] = *(const uint4*)&A[(size_t)(row0 + r) * K + lc * 8];
        vb[i] = *(const uint4*)&B[(size_t)(col0 + r) * K + lc * 8];
    }
#pragma unroll
    for (int i = 0; i < 2; i++) {
        const int r = lr0 + i * 64;
        const int off = SWOFF(r, lc * 16);
        *(uint4*)(As[0] + off) = va[i];
        *(uint4*)(Bs[0] + off) = vb[i];
    }
    __syncthreads();

    const int NT = K / 32;
    for (int it = 0; it < NT; it++) {
        const int buf  = it & 1;
        const bool more = (it + 1) < NT;

        if (more) {
            const int k0 = (it + 1) * 32;
#pragma unroll
            for (int i = 0; i < 2; i++) {
                const int r = lr0 + i * 64;
                va[i] = *(const uint4*)&A[(size_t)(row0 + r) * K + k0 + lc * 8];
                vb[i] = *(const uint4*)&B[(size_t)(col0 + r) * K + k0 + lc * 8];
            }
        }

        const char* as = As[buf];
        const char* bs = Bs[buf];
#pragma unroll
        for (int kk = 0; kk < 32; kk += 16) {
            const int ba = (kk + 2 * t) * 2;     // byte offset of k pair
            uint32_t af[4][4], bf[4][2];
#pragma unroll
            for (int mi = 0; mi < 4; mi++) {
                const int r = wm * 64 + mi * 16 + g;
                af[mi][0] = *(const uint32_t*)(as + SWOFF(r,     ba));
                af[mi][1] = *(const uint32_t*)(as + SWOFF(r + 8, ba));
                af[mi][2] = *(const uint32_t*)(as + SWOFF(r,     ba + 16));
                af[mi][3] = *(const uint32_t*)(as + SWOFF(r + 8, ba + 16));
            }
#pragma unroll
            for (int ni = 0; ni < 4; ni++) {
                const int r = wn * 32 + ni * 8 + g;
                bf[ni][0] = *(const uint32_t*)(bs + SWOFF(r, ba));
                bf[ni][1] = *(const uint32_t*)(bs + SWOFF(r, ba + 16));
            }
#pragma unroll
            for (int mi = 0; mi < 4; mi++)
#pragma unroll
                for (int ni = 0; ni < 4; ni++)
                    mma_f16(acc[mi][ni], af[mi], bf[ni][0], bf[ni][1]);
        }

        if (more) {
            const int nb = buf ^ 1;
#pragma unroll
            for (int i = 0; i < 2; i++) {
                const int r = lr0 + i * 64;
                const int off = SWOFF(r, lc * 16);
                *(uint4*)(As[nb] + off) = va[i];
                *(uint4*)(Bs[nb] + off) = vb[i];
            }
        }
        __syncthreads();
    }

    // epilogue: c0=(g,2t), c1=(g,2t+1), c2=(g+8,2t), c3=(g+8,2t+1)
#pragma unroll
    for (int mi = 0; mi < 4; mi++) {
        const int row = row0 + wm * 64 + mi * 16 + g;
#pragma unroll
        for (int ni = 0; ni < 4; ni++) {
            const int col = col0 + wn * 32 + ni * 8 + 2 * t;
            *(float2*)&C[(size_t)row * N + col] =
                make_float2(acc[mi][ni][0], acc[mi][ni][1]);
            *(float2*)&C[(size_t)(row + 8) * N + col] =
                make_float2(acc[mi][ni][2], acc[mi][ni][3]);
        }
    }
}

// ---------------------------------------------------------------------------
// RoPE -> fp16 tensors for attention.
// ---------------------------------------------------------------------------
#define QSCALE 0.18033688011112042f   // 0.125 * log2(e)

__global__ __launch_bounds__(256) void rope_fp16(const float* __restrict__ qkv,
                                                 const float* __restrict__ fc,
                                                 __half* __restrict__ Qh,
                                                 __half* __restrict__ Kh,
                                                 __half* __restrict__ Vth) {
    const int s   = blockIdx.x;
    const int tid = threadIdx.x;
    const float* row = qkv + (size_t)s * QKV_N;

    for (int i = tid; i < NH * (HD / 2); i += 256) {
        int h = i >> 5, d2 = i & 31;
        float x0 = row[h * HD + 2 * d2];
        float x1 = row[h * HD + 2 * d2 + 1];
        float c  = fc[s * HD + 2 * d2];
        float sn = fc[s * HD + 2 * d2 + 1];
        float y0 = (x0 * c - x1 * sn) * QSCALE;
        float y1 = (x1 * c + x0 * sn) * QSCALE;
        *(__half2*)&Qh[((size_t)h * S + s) * HD + 2 * d2] = __floats2half2_rn(y0, y1);
    }
    {
        int h = tid >> 5, d2 = tid & 31;
        float x0 = row[D + h * HD + 2 * d2];
        float x1 = row[D + h * HD + 2 * d2 + 1];
        float c  = fc[s * HD + 2 * d2];
        float sn = fc[s * HD + 2 * d2 + 1];
        float y0 = x0 * c - x1 * sn;
        float y1 = x1 * c + x0 * sn;
        *(__half2*)&Kh[((size_t)h * S + s) * HD + 2 * d2] = __floats2half2_rn(y0, y1);
    }
    for (int i = tid; i < NKV * HD; i += 256) {
        int h = i >> 6, d = i & 63;
        Vth[((size_t)h * HD + d) * S + s] = __float2half_rn(row[D + NKV * HD + i]);
    }
}

// ---------------------------------------------------------------------------
// Tensor-core causal flash attention (fp16 mma, fp32 acc, no-max softmax).
// Output written directly in fp16 (feeds gemm_h).
// ---------------------------------------------------------------------------
#define AQ 128
#define AK 64
#define KLD 88   // half stride: 176B, conflict-free frag loads

__global__ __launch_bounds__(256) void attn_mma(const __half* __restrict__ Qh,
                                                const __half* __restrict__ Kh,
                                                const __half* __restrict__ Vth,
                                                __half* __restrict__ O) {
    __shared__ __half Ks[AK][KLD];   // [kv][d]
    __shared__ __half Vs[HD][KLD];   // [d][kv]

    const int h    = blockIdx.y;
    const int kh   = h >> 2;
    const int qb   = gridDim.x - 1 - blockIdx.x;
    const int tid  = threadIdx.x;
    const int lane = tid & 31;
    const int w    = tid >> 5;
    const int g    = lane >> 2;
    const int t    = lane & 3;
    const int bq   = qb * AQ + w * 16;

    uint32_t qf[4][4];
    const __half* Qr0 = Qh + ((size_t)h * S + bq + g) * HD;
    const __half* Qr8 = Qr0 + 8 * HD;
#pragma unroll
    for (int kc = 0; kc < 4; kc++) {
        qf[kc][0] = *(const uint32_t*)(Qr0 + 16 * kc + 2 * t);
        qf[kc][1] = *(const uint32_t*)(Qr8 + 16 * kc + 2 * t);
        qf[kc][2] = *(const uint32_t*)(Qr0 + 16 * kc + 2 * t + 8);
        qf[kc][3] = *(const uint32_t*)(Qr8 + 16 * kc + 2 * t + 8);
    }

    float o[8][4];
#pragma unroll
    for (int nn = 0; nn < 8; nn++)
#pragma unroll
        for (int e = 0; e < 4; e++) o[nn][e] = 0.f;
    float lacc[4] = {0.f, 0.f, 0.f, 0.f};
    const uint32_t ONES = 0x3C003C00u;

    const int ntiles = (qb + 1) * (AQ / AK);
    for (int tt = 0; tt < ntiles; tt++) {
        const int kv0 = tt * AK;
#pragma unroll
        for (int i = 0; i < 2; i++) {
            const int idx = tid + i * 256;
            const int r = idx >> 3, c = (idx & 7) * 8;
            *(float4*)&Ks[r][c] =
                *(const float4*)&Kh[((size_t)kh * S + kv0 + r) * HD + c];
            *(float4*)&Vs[r][c] =
                *(const float4*)&Vth[((size_t)kh * HD + r) * S + kv0 + c];
        }
        __syncthreads();

        if (kv0 <= bq + 15) {
            float sc[8][4];
#pragma unroll
            for (int nn = 0; nn < 8; nn++) {
                sc[nn][0] = sc[nn][1] = sc[nn][2] = sc[nn][3] = 0.f;
#pragma unroll
                for (int kc = 0; kc < 4; kc++) {
                    uint32_t b0 = *(const uint32_t*)&Ks[nn * 8 + g][16 * kc + 2 * t];
                    uint32_t b1 = *(const uint32_t*)&Ks[nn * 8 + g][16 * kc + 2 * t + 8];
                    mma_f16(sc[nn], qf[kc], b0, b1);
                }
            }
            if (kv0 + AK - 1 > bq) {
                const int rg  = bq + g;
                const int rg8 = rg + 8;
#pragma unroll
                for (int nn = 0; nn < 8; nn++) {
                    const int col = kv0 + nn * 8 + 2 * t;
                    if (col     > rg ) sc[nn][0] = -30.f;
                    if (col + 1 > rg ) sc[nn][1] = -30.f;
                    if (col     > rg8) sc[nn][2] = -30.f;
                    if (col + 1 > rg8) sc[nn][3] = -30.f;
                }
            }
            uint32_t p[8][2];
#pragma unroll
            for (int nn = 0; nn < 8; nn++) {
                p[nn][0] = ex2_h2(pack_h2(sc[nn][0], sc[nn][1]));
                p[nn][1] = ex2_h2(pack_h2(sc[nn][2], sc[nn][3]));
            }
#pragma unroll
            for (int c = 0; c < 4; c++) {
                uint32_t a[4] = {p[2 * c][0], p[2 * c][1],
                                 p[2 * c + 1][0], p[2 * c + 1][1]};
                mma_f16(lacc, a, ONES, ONES);
#pragma unroll
                for (int nn = 0; nn < 8; nn++) {
                    uint32_t b0 = *(const uint32_t*)&Vs[nn * 8 + g][16 * c + 2 * t];
                    uint32_t b1 = *(const uint32_t*)&Vs[nn * 8 + g][16 * c + 2 * t + 8];
                    mma_f16(o[nn], a, b0, b1);
                }
            }
        }
        __syncthreads();
    }

    const float invg  = 1.f / lacc[0];
    const float invg8 = 1.f / lacc[2];
#pragma unroll
    for (int nn = 0; nn < 8; nn++) {
        const int col = h * HD + nn * 8 + 2 * t;
        *(__half2*)&O[(size_t)(bq + g) * D + col] =
            __floats2half2_rn(o[nn][0] * invg, o[nn][1] * invg);
        *(__half2*)&O[(size_t)(bq + g + 8) * D + col] =
            __floats2half2_rn(o[nn][2] * invg8, o[nn][3] * invg8);
    }
}

// ---------------------------------------------------------------------------
// Launch
// ---------------------------------------------------------------------------
extern "C" void kernel_launch(void* const* d_in, const int* in_sizes, int n_in,
                              void* d_out, int out_size) {
    const float* hs   = (const float*)d_in[0];   // [1, 2048, 2048]
    const float* fc   = (const float*)d_in[1];   // [2048, 32, 2]
    const float* wqkv = (const float*)d_in[2];   // [3072, 2048]
    const float* wo   = (const float*)d_in[3];   // [2048, 2048]
    float* out = (float*)d_out;                  // [1, 2048, 2048]

    float  *p_qkv;
    __half *p_hsh, *p_wqkvh, *p_woh, *p_qh, *p_kh, *p_vth, *p_attnh;
    cudaGetSymbolAddress((void**)&p_qkv,   g_qkv);
    cudaGetSymbolAddress((void**)&p_hsh,   g_hsh);
    cudaGetSymbolAddress((void**)&p_wqkvh, g_wqkvh);
    cudaGetSymbolAddress((void**)&p_woh,   g_woh);
    cudaGetSymbolAddress((void**)&p_qh,    g_qh);
    cudaGetSymbolAddress((void**)&p_kh,    g_kh);
    cudaGetSymbolAddress((void**)&p_vth,   g_vth);
    cudaGetSymbolAddress((void**)&p_attnh, g_attnh);

    // 0) fp16 conversions
    cvt_h<<<(S * D / 4 + 255) / 256, 256>>>(hs, p_hsh, S * D / 4);
    cvt_h<<<(QKV_N * D / 4 + 255) / 256, 256>>>(wqkv, p_wqkvh, QKV_N * D / 4);
    cvt_h<<<(D * D / 4 + 255) / 256, 256>>>(wo, p_woh, D * D / 4);

    // 1) qkv = hs @ wqkv^T  (fp16 in, f32 out)
    gemm_h<<<dim3(QKV_N / 128, S / 128), 256>>>(p_hsh, p_wqkvh, p_qkv, S, QKV_N, D);
    // 2) RoPE -> fp16 Q (pre-scaled), K, V^T
    rope_fp16<<<S, 256>>>(p_qkv, fc, p_qh, p_kh, p_vth);
    // 3) tensor-core causal attention (fp16 out)
    attn_mma<<<dim3(S / AQ, NH), 256>>>(p_qh, p_kh, p_vth, p_attnh);
    // 4) out = attn @ wo^T
    gemm_h<<<dim3(D / 128, S / 128), 256>>>(p_attnh, p_woh, out, S, D, D);
}

// round 7
// speedup vs baseline: 13.4845x; 1.1974x over previous
#include <cuda_runtime.h>
#include <cuda_fp16.h>
#include <math.h>
#include <stdint.h>

// Problem constants
#define S    2048
#define D    2048
#define NH   32
#define NKV  8
#define HD   64
#define QKV_N 3072   // (32 + 16) * 64

// ---------------------------------------------------------------------------
// Scratch (device globals — no allocation allowed)
// ---------------------------------------------------------------------------
__device__ float  g_qkv[(size_t)S * QKV_N];       // [s, 3072] f32
__device__ __half g_hsh  [(size_t)S * D];         // hs in fp16
__device__ __half g_wqkvh[(size_t)QKV_N * D];     // wqkv in fp16
__device__ __half g_woh  [(size_t)D * D];         // wo in fp16
__device__ __half g_qh [(size_t)NH  * S * HD];    // [h, s, d] (pre-scaled)
__device__ __half g_kh [(size_t)NKV * S * HD];    // [kh, s, d]
__device__ __half g_vth[(size_t)NKV * HD * S];    // [kh, d, s] (transposed)
__device__ __half g_attnh[(size_t)S * D];         // attention out, fp16

__device__ __forceinline__ void mma_f16(float* d, const uint32_t* a,
                                        uint32_t b0, uint32_t b1) {
    asm volatile(
        "mma.sync.aligned.m16n8k16.row.col.f32.f16.f16.f32 "
        "{%0,%1,%2,%3}, {%4,%5,%6,%7}, {%8,%9}, {%0,%1,%2,%3};"
        : "+f"(d[0]), "+f"(d[1]), "+f"(d[2]), "+f"(d[3])
        : "r"(a[0]), "r"(a[1]), "r"(a[2]), "r"(a[3]), "r"(b0), "r"(b1));
}

__device__ __forceinline__ void ldsm_x4(uint32_t* r, uint32_t addr) {
    asm volatile("ldmatrix.sync.aligned.m8n8.x4.shared.b16 {%0,%1,%2,%3}, [%4];"
                 : "=r"(r[0]), "=r"(r[1]), "=r"(r[2]), "=r"(r[3]) : "r"(addr));
}

__device__ __forceinline__ void cp16(uint32_t dst, const void* src) {
    asm volatile("cp.async.cg.shared.global [%0], [%1], 16;" :: "r"(dst), "l"(src));
}
#define CP_COMMIT() asm volatile("cp.async.commit_group;" ::: "memory")
#define CP_WAIT0()  asm volatile("cp.async.wait_group 0;" ::: "memory")

__device__ __forceinline__ uint32_t ex2_h2(uint32_t x) {
    uint32_t r;
    asm("ex2.approx.f16x2 %0, %1;" : "=r"(r) : "r"(x));
    return r;
}
__device__ __forceinline__ uint32_t pack_h2(float lo, float hi) {
    __half2 h = __floats2half2_rn(lo, hi);
    return *(uint32_t*)&h;
}

// ---------------------------------------------------------------------------
// f32 -> f16 conversion (float4 granularity)
// ---------------------------------------------------------------------------
__global__ __launch_bounds__(256) void cvt_h(const float* __restrict__ src,
                                             __half* __restrict__ dst, int n4) {
    int i = blockIdx.x * 256 + threadIdx.x;
    if (i < n4) {
        float4 v = ((const float4*)src)[i];
        __half2 h01 = __floats2half2_rn(v.x, v.y);
        __half2 h23 = __floats2half2_rn(v.z, v.w);
        ((uint2*)dst)[i] = make_uint2(*(uint32_t*)&h01, *(uint32_t*)&h23);
    }
}

// ---------------------------------------------------------------------------
// fp16 tensor-core GEMM: C[M,N](f32) = A[M,K](f16) @ B[N,K](f16)^T.
// CTA 128x128, 8 warps (2m x 4n), warp tile 64x32, k-tile 32 halves.
// cp.async double-buffered smem (XOR-chunk swizzle), ldmatrix.x4 frag loads.
// ---------------------------------------------------------------------------
// byte offset within one 128x64B buffer
#define SWB(row, b) ((row) * 64 + (((((b) >> 4) ^ (((row) >> 1) & 3)) << 4) | ((b) & 15)))

__global__ __launch_bounds__(256) void gemm_h(const __half* __restrict__ A,
                                              const __half* __restrict__ B,
                                              float* __restrict__ C,
                                              int M, int N, int K) {
    __shared__ __align__(16) char As[2][8192];
    __shared__ __align__(16) char Bs[2][8192];

    const int tid  = threadIdx.x;
    const int lane = tid & 31;
    const int wid  = tid >> 5;
    const int wm   = wid >> 2;          // 0..1
    const int wn   = wid & 3;           // 0..3
    const int g    = lane >> 2;         // 0..7
    const int t    = lane & 3;          // 0..3
    const int row0 = blockIdx.y * 128;
    const int col0 = blockIdx.x * 128;

    const uint32_t asb = (uint32_t)__cvta_generic_to_shared(&As[0][0]);
    const uint32_t bsb = (uint32_t)__cvta_generic_to_shared(&Bs[0][0]);

    // loader coords: each thread moves 16B x2 per operand per k-tile
    const int lr0 = tid >> 2;           // rows 0..63 (and +64)
    const int lc  = tid & 3;            // 16B chunk
    const uint32_t st0 = SWB(lr0, lc * 16);
    const uint32_t st1 = SWB(lr0 + 64, lc * 16);
    const __half* Ap0 = A + (size_t)(row0 + lr0) * K + lc * 8;
    const __half* Ap1 = Ap0 + (size_t)64 * K;
    const __half* Bp0 = B + (size_t)(col0 + lr0) * K + lc * 8;
    const __half* Bp1 = Bp0 + (size_t)64 * K;

    // ldmatrix lane geometry
    const int a_r = wm * 64 + ((lane >> 3) & 1) * 8 + (lane & 7);
    const int a_c = (lane >> 4) * 16;          // k-chunk byte
    const int b_r = wn * 32 + (lane >> 4) * 8 + (lane & 7);
    const int b_c = ((lane >> 3) & 1) * 16;

    float acc[4][4][4];
#pragma unroll
    for (int mi = 0; mi < 4; mi++)
#pragma unroll
        for (int ni = 0; ni < 4; ni++)
#pragma unroll
            for (int e = 0; e < 4; e++) acc[mi][ni][e] = 0.f;

    // prologue: tile 0
    cp16(asb + st0, Ap0); cp16(asb + st1, Ap1);
    cp16(bsb + st0, Bp0); cp16(bsb + st1, Bp1);
    CP_COMMIT();

    const int NT = K / 32;
    for (int it = 0; it < NT; it++) {
        const int buf = it & 1;
        CP_WAIT0();
        __syncthreads();

        if (it + 1 < NT) {
            const int k0 = (it + 1) * 32;
            const uint32_t nb = (buf ^ 1) * 8192;
            cp16(asb + nb + st0, Ap0 + k0); cp16(asb + nb + st1, Ap1 + k0);
            cp16(bsb + nb + st0, Bp0 + k0); cp16(bsb + nb + st1, Bp1 + k0);
            CP_COMMIT();
        }

        const uint32_t ab = asb + buf * 8192;
        const uint32_t bb = bsb + buf * 8192;
#pragma unroll
        for (int kk2 = 0; kk2 < 2; kk2++) {
            const int kb = kk2 * 32;    // byte base of this k16 chunk
            uint32_t af[4][4], bf[2][4];
#pragma unroll
            for (int mi = 0; mi < 4; mi++)
                ldsm_x4(af[mi], ab + SWB(a_r + mi * 16, kb + a_c));
#pragma unroll
            for (int np = 0; np < 2; np++)
                ldsm_x4(bf[np], bb + SWB(b_r + np * 16, kb + b_c));
#pragma unroll
            for (int mi = 0; mi < 4; mi++)
#pragma unroll
                for (int ni = 0; ni < 4; ni++)
                    mma_f16(acc[mi][ni], af[mi],
                            bf[ni >> 1][(ni & 1) * 2], bf[ni >> 1][(ni & 1) * 2 + 1]);
        }
        __syncthreads();
    }

    // epilogue: c0=(g,2t), c1=(g,2t+1), c2=(g+8,2t), c3=(g+8,2t+1)
#pragma unroll
    for (int mi = 0; mi < 4; mi++) {
        const int row = row0 + wm * 64 + mi * 16 + g;
#pragma unroll
        for (int ni = 0; ni < 4; ni++) {
            const int col = col0 + wn * 32 + ni * 8 + 2 * t;
            *(float2*)&C[(size_t)row * N + col] =
                make_float2(acc[mi][ni][0], acc[mi][ni][1]);
            *(float2*)&C[(size_t)(row + 8) * N + col] =
                make_float2(acc[mi][ni][2], acc[mi][ni][3]);
        }
    }
}

// ---------------------------------------------------------------------------
// RoPE -> fp16 tensors for attention.
// ---------------------------------------------------------------------------
#define QSCALE 0.18033688011112042f   // 0.125 * log2(e)

__global__ __launch_bounds__(256) void rope_fp16(const float* __restrict__ qkv,
                                                 const float* __restrict__ fc,
                                                 __half* __restrict__ Qh,
                                                 __half* __restrict__ Kh,
                                                 __half* __restrict__ Vth) {
    const int s   = blockIdx.x;
    const int tid = threadIdx.x;
    const float* row = qkv + (size_t)s * QKV_N;

    for (int i = tid; i < NH * (HD / 2); i += 256) {
        int h = i >> 5, d2 = i & 31;
        float x0 = row[h * HD + 2 * d2];
        float x1 = row[h * HD + 2 * d2 + 1];
        float c  = fc[s * HD + 2 * d2];
        float sn = fc[s * HD + 2 * d2 + 1];
        float y0 = (x0 * c - x1 * sn) * QSCALE;
        float y1 = (x1 * c + x0 * sn) * QSCALE;
        *(__half2*)&Qh[((size_t)h * S + s) * HD + 2 * d2] = __floats2half2_rn(y0, y1);
    }
    {
        int h = tid >> 5, d2 = tid & 31;
        float x0 = row[D + h * HD + 2 * d2];
        float x1 = row[D + h * HD + 2 * d2 + 1];
        float c  = fc[s * HD + 2 * d2];
        float sn = fc[s * HD + 2 * d2 + 1];
        float y0 = x0 * c - x1 * sn;
        float y1 = x1 * c + x0 * sn;
        *(__half2*)&Kh[((size_t)h * S + s) * HD + 2 * d2] = __floats2half2_rn(y0, y1);
    }
    for (int i = tid; i < NKV * HD; i += 256) {
        int h = i >> 6, d = i & 63;
        Vth[((size_t)h * HD + d) * S + s] = __float2half_rn(row[D + NKV * HD + i]);
    }
}

// ---------------------------------------------------------------------------
// Tensor-core causal flash attention (fp16 mma, fp32 acc, no-max softmax).
// ---------------------------------------------------------------------------
#define AQ 128
#define AK 64
#define KLD 88   // half stride: 176B, conflict-free frag loads

__global__ __launch_bounds__(256) void attn_mma(const __half* __restrict__ Qh,
                                                const __half* __restrict__ Kh,
                                                const __half* __restrict__ Vth,
                                                __half* __restrict__ O) {
    __shared__ __half Ks[AK][KLD];   // [kv][d]
    __shared__ __half Vs[HD][KLD];   // [d][kv]

    const int h    = blockIdx.y;
    const int kh   = h >> 2;
    const int qb   = gridDim.x - 1 - blockIdx.x;
    const int tid  = threadIdx.x;
    const int lane = tid & 31;
    const int w    = tid >> 5;
    const int g    = lane >> 2;
    const int t    = lane & 3;
    const int bq   = qb * AQ + w * 16;

    uint32_t qf[4][4];
    const __half* Qr0 = Qh + ((size_t)h * S + bq + g) * HD;
    const __half* Qr8 = Qr0 + 8 * HD;
#pragma unroll
    for (int kc = 0; kc < 4; kc++) {
        qf[kc][0] = *(const uint32_t*)(Qr0 + 16 * kc + 2 * t);
        qf[kc][1] = *(const uint32_t*)(Qr8 + 16 * kc + 2 * t);
        qf[kc][2] = *(const uint32_t*)(Qr0 + 16 * kc + 2 * t + 8);
        qf[kc][3] = *(const uint32_t*)(Qr8 + 16 * kc + 2 * t + 8);
    }

    float o[8][4];
#pragma unroll
    for (int nn = 0; nn < 8; nn++)
#pragma unroll
        for (int e = 0; e < 4; e++) o[nn][e] = 0.f;
    float lacc[4] = {0.f, 0.f, 0.f, 0.f};
    const uint32_t ONES = 0x3C003C00u;

    const int ntiles = (qb + 1) * (AQ / AK);
    for (int tt = 0; tt < ntiles; tt++) {
        const int kv0 = tt * AK;
#pragma unroll
        for (int i = 0; i < 2; i++) {
            const int idx = tid + i * 256;
            const int r = idx >> 3, c = (idx & 7) * 8;
            *(float4*)&Ks[r][c] =
                *(const float4*)&Kh[((size_t)kh * S + kv0 + r) * HD + c];
            *(float4*)&Vs[r][c] =
                *(const float4*)&Vth[((size_t)kh * HD + r) * S + kv0 + c];
        }
        __syncthreads();

        if (kv0 <= bq + 15) {
            float sc[8][4];
#pragma unroll
            for (int nn = 0; nn < 8; nn++) {
                sc[nn][0] = sc[nn][1] = sc[nn][2] = sc[nn][3] = 0.f;
#pragma unroll
                for (int kc = 0; kc < 4; kc++) {
                    uint32_t b0 = *(const uint32_t*)&Ks[nn * 8 + g][16 * kc + 2 * t];
                    uint32_t b1 = *(const uint32_t*)&Ks[nn * 8 + g][16 * kc + 2 * t + 8];
                    mma_f16(sc[nn], qf[kc], b0, b1);
                }
            }
            if (kv0 + AK - 1 > bq) {
                const int rg  = bq + g;
                const int rg8 = rg + 8;
#pragma unroll
                for (int nn = 0; nn < 8; nn++) {
                    const int col = kv0 + nn * 8 + 2 * t;
                    if (col     > rg ) sc[nn][0] = -30.f;
                    if (col + 1 > rg ) sc[nn][1] = -30.f;
                    if (col     > rg8) sc[nn][2] = -30.f;
                    if (col + 1 > rg8) sc[nn][3] = -30.f;
                }
            }
            uint32_t p[8][2];
#pragma unroll
            for (int nn = 0; nn < 8; nn++) {
                p[nn][0] = ex2_h2(pack_h2(sc[nn][0], sc[nn][1]));
                p[nn][1] = ex2_h2(pack_h2(sc[nn][2], sc[nn][3]));
            }
#pragma unroll
            for (int c = 0; c < 4; c++) {
                uint32_t a[4] = {p[2 * c][0], p[2 * c][1],
                                 p[2 * c + 1][0], p[2 * c + 1][1]};
                mma_f16(lacc, a, ONES, ONES);
#pragma unroll
                for (int nn = 0; nn < 8; nn++) {
                    uint32_t b0 = *(const uint32_t*)&Vs[nn * 8 + g][16 * c + 2 * t];
                    uint32_t b1 = *(const uint32_t*)&Vs[nn * 8 + g][16 * c + 2 * t + 8];
                    mma_f16(o[nn], a, b0, b1);
                }
            }
        }
        __syncthreads();
    }

    const float invg  = 1.f / lacc[0];
    const float invg8 = 1.f / lacc[2];
#pragma unroll
    for (int nn = 0; nn < 8; nn++) {
        const int col = h * HD + nn * 8 + 2 * t;
        *(__half2*)&O[(size_t)(bq + g) * D + col] =
            __floats2half2_rn(o[nn][0] * invg, o[nn][1] * invg);
        *(__half2*)&O[(size_t)(bq + g + 8) * D + col] =
            __floats2half2_rn(o[nn][2] * invg8, o[nn][3] * invg8);
    }
}

// ---------------------------------------------------------------------------
// Launch
// ---------------------------------------------------------------------------
extern "C" void kernel_launch(void* const* d_in, const int* in_sizes, int n_in,
                              void* d_out, int out_size) {
    const float* hs   = (const float*)d_in[0];   // [1, 2048, 2048]
    const float* fc   = (const float*)d_in[1];   // [2048, 32, 2]
    const float* wqkv = (const float*)d_in[2];   // [3072, 2048]
    const float* wo   = (const float*)d_in[3];   // [2048, 2048]
    float* out = (float*)d_out;                  // [1, 2048, 2048]

    float  *p_qkv;
    __half *p_hsh, *p_wqkvh, *p_woh, *p_qh, *p_kh, *p_vth, *p_attnh;
    cudaGetSymbolAddress((void**)&p_qkv,   g_qkv);
    cudaGetSymbolAddress((void**)&p_hsh,   g_hsh);
    cudaGetSymbolAddress((void**)&p_wqkvh, g_wqkvh);
    cudaGetSymbolAddress((void**)&p_woh,   g_woh);
    cudaGetSymbolAddress((void**)&p_qh,    g_qh);
    cudaGetSymbolAddress((void**)&p_kh,    g_kh);
    cudaGetSymbolAddress((void**)&p_vth,   g_vth);
    cudaGetSymbolAddress((void**)&p_attnh, g_attnh);

    // 0) fp16 conversions
    cvt_h<<<(S * D / 4 + 255) / 256, 256>>>(hs, p_hsh, S * D / 4);
    cvt_h<<<(QKV_N * D / 4 + 255) / 256, 256>>>(wqkv, p_wqkvh, QKV_N * D / 4);
    cvt_h<<<(D * D / 4 + 255) / 256, 256>>>(wo, p_woh, D * D / 4);

    // 1) qkv = hs @ wqkv^T  (fp16 in, f32 out)
    gemm_h<<<dim3(QKV_N / 128, S / 128), 256>>>(p_hsh, p_wqkvh, p_qkv, S, QKV_N, D);
    // 2) RoPE -> fp16 Q (pre-scaled), K, V^T
    rope_fp16<<<S, 256>>>(p_qkv, fc, p_qh, p_kh, p_vth);
    // 3) tensor-core causal attention (fp16 out)
    attn_mma<<<dim3(S / AQ, NH), 256>>>(p_qh, p_kh, p_vth, p_attnh);
    // 4) out = attn @ wo^T
    gemm_h<<<dim3(D / 128, S / 128), 256>>>(p_attnh, p_woh, out, S, D, D);
}